// round 6
// baseline (speedup 1.0000x reference)
#include <cuda_runtime.h>
#include <cuda_fp16.h>
#include <stdint.h>

#define N_NODES  50000
#define N_EDGES  800000
#define IN_F     128
#define OUT_F    128

#define SCAN_T   256
#define SCAN_B   ((N_NODES + SCAN_T - 1) / SCAN_T)   // 196

#define NUM_SM   148
#define TILE_M   128
#define N_TILES  ((N_NODES + TILE_M - 1) / TILE_M)   // 391

// -------------------- device scratch (no allocation allowed) ---------------
__device__ __align__(16) float  g_agg[N_NODES * IN_F];   // normalized h rows
__device__ __align__(16) __half g_xh[N_NODES * IN_F];    // fp16 copy of x
__device__ int   g_cnt[N_NODES];
__device__ int   g_off[N_NODES];
__device__ int   g_cur[N_NODES];
__device__ int   g_srcs[N_EDGES];
__device__ int   g_bsums[SCAN_B];

// -------------------- 0) convert x->fp16 AND zero histogram ----------------
__global__ void convert_zero_kernel(const float4* __restrict__ x4) {
    const int tid    = blockIdx.x * blockDim.x + threadIdx.x;
    const int stride = gridDim.x * blockDim.x;
    uint2* xh2 = reinterpret_cast<uint2*>(g_xh);
    const int n4 = N_NODES * IN_F / 4;   // 1.6M
    for (int i = tid; i < n4; i += stride) {
        float4 v = x4[i];
        __half2 h0 = __floats2half2_rn(v.x, v.y);
        __half2 h1 = __floats2half2_rn(v.z, v.w);
        uint2 p;
        p.x = *reinterpret_cast<unsigned*>(&h0);
        p.y = *reinterpret_cast<unsigned*>(&h1);
        xh2[i] = p;
    }
    for (int i = tid; i < N_NODES; i += stride)
        g_cnt[i] = 0;
}

// -------------------- 1) histogram of destinations (4 edges/thread) --------
__global__ void hist_kernel(const int* __restrict__ ei) {
    const int e4 = blockIdx.x * blockDim.x + threadIdx.x;
    if (e4 >= N_EDGES / 4) return;
    int4 d = reinterpret_cast<const int4*>(ei + N_EDGES)[e4];
    d.x = min(max(d.x, 0), N_NODES - 1);
    d.y = min(max(d.y, 0), N_NODES - 1);
    d.z = min(max(d.z, 0), N_NODES - 1);
    d.w = min(max(d.w, 0), N_NODES - 1);
    atomicAdd(&g_cnt[d.x], 1);
    atomicAdd(&g_cnt[d.y], 1);
    atomicAdd(&g_cnt[d.z], 1);
    atomicAdd(&g_cnt[d.w], 1);
}

// -------------------- 2) scanA: per-block sums -----------------------------
__global__ void scanA_kernel() {
    __shared__ int s[SCAN_T];
    int gid = blockIdx.x * SCAN_T + threadIdx.x;
    s[threadIdx.x] = (gid < N_NODES) ? g_cnt[gid] : 0;
    __syncthreads();
    #pragma unroll
    for (int o = SCAN_T / 2; o > 0; o >>= 1) {
        if (threadIdx.x < o) s[threadIdx.x] += s[threadIdx.x + o];
        __syncthreads();
    }
    if (threadIdx.x == 0) g_bsums[blockIdx.x] = s[0];
}

// -------------------- 3) scanB: full exclusive scan ------------------------
__global__ void scanB_kernel() {
    __shared__ int sb[SCAN_T];
    __shared__ int st[SCAN_T];
    const int tid = threadIdx.x;

    int bv = (tid < SCAN_B) ? g_bsums[tid] : 0;
    sb[tid] = bv;
    __syncthreads();
    #pragma unroll
    for (int o = 1; o < SCAN_T; o <<= 1) {
        int t = (tid >= o) ? sb[tid - o] : 0;
        __syncthreads();
        sb[tid] += t;
        __syncthreads();
    }
    const int base = (blockIdx.x > 0) ? sb[blockIdx.x - 1] : 0;

    const int gid = blockIdx.x * SCAN_T + tid;
    int c = (gid < N_NODES) ? g_cnt[gid] : 0;
    st[tid] = c;
    __syncthreads();
    #pragma unroll
    for (int o = 1; o < SCAN_T; o <<= 1) {
        int t = (tid >= o) ? st[tid - o] : 0;
        __syncthreads();
        st[tid] += t;
        __syncthreads();
    }
    if (gid < N_NODES) {
        const int excl = base + st[tid] - c;
        g_off[gid] = excl;
        g_cur[gid] = excl;
    }
}

// -------------------- 4) bucket-fill -----------------------------------
__global__ void fill_kernel(const int* __restrict__ ei) {
    const int e4 = blockIdx.x * blockDim.x + threadIdx.x;
    if (e4 >= N_EDGES / 4) return;
    int4 s = reinterpret_cast<const int4*>(ei)[e4];
    int4 d = reinterpret_cast<const int4*>(ei + N_EDGES)[e4];
    s.x = min(max(s.x, 0), N_NODES - 1);
    s.y = min(max(s.y, 0), N_NODES - 1);
    s.z = min(max(s.z, 0), N_NODES - 1);
    s.w = min(max(s.w, 0), N_NODES - 1);
    d.x = min(max(d.x, 0), N_NODES - 1);
    d.y = min(max(d.y, 0), N_NODES - 1);
    d.z = min(max(d.z, 0), N_NODES - 1);
    d.w = min(max(d.w, 0), N_NODES - 1);
    int p0 = atomicAdd(&g_cur[d.x], 1);
    int p1 = atomicAdd(&g_cur[d.y], 1);
    int p2 = atomicAdd(&g_cur[d.z], 1);
    int p3 = atomicAdd(&g_cur[d.w], 1);
    g_srcs[p0] = s.x;
    g_srcs[p1] = s.y;
    g_srcs[p2] = s.z;
    g_srcs[p3] = s.w;
}

// -------------------- 5) gather-aggregate (fp16 source) --------------------
// One warp per node; lane covers 4 features = one uint2 (2 half2) per edge.
__device__ __forceinline__ void acc_h2(float4& a, uint2 p) {
    __half2 h0 = *reinterpret_cast<__half2*>(&p.x);
    __half2 h1 = *reinterpret_cast<__half2*>(&p.y);
    float2 f0 = __half22float2(h0);
    float2 f1 = __half22float2(h1);
    a.x += f0.x; a.y += f0.y; a.z += f1.x; a.w += f1.y;
}

__global__ void __launch_bounds__(256)
agg_kernel() {
    const int node = (blockIdx.x * blockDim.x + threadIdx.x) >> 5;
    if (node >= N_NODES) return;
    const int lane = threadIdx.x & 31;

    const int start = g_off[node];
    const int cnt   = g_cnt[node];
    const int end   = start + cnt;

    const uint2* xh2 = reinterpret_cast<const uint2*>(g_xh);

    float4 a0 = make_float4(0.f, 0.f, 0.f, 0.f);
    float4 a1 = make_float4(0.f, 0.f, 0.f, 0.f);
    float4 a2 = make_float4(0.f, 0.f, 0.f, 0.f);
    float4 a3 = make_float4(0.f, 0.f, 0.f, 0.f);

    int e = start;
    for (; e + 7 < end; e += 8) {
        int s0 = g_srcs[e],     s1 = g_srcs[e + 1];
        int s2 = g_srcs[e + 2], s3 = g_srcs[e + 3];
        int s4 = g_srcs[e + 4], s5 = g_srcs[e + 5];
        int s6 = g_srcs[e + 6], s7 = g_srcs[e + 7];
        uint2 p0 = __ldg(&xh2[s0 * 32 + lane]);
        uint2 p1 = __ldg(&xh2[s1 * 32 + lane]);
        uint2 p2 = __ldg(&xh2[s2 * 32 + lane]);
        uint2 p3 = __ldg(&xh2[s3 * 32 + lane]);
        uint2 p4 = __ldg(&xh2[s4 * 32 + lane]);
        uint2 p5 = __ldg(&xh2[s5 * 32 + lane]);
        uint2 p6 = __ldg(&xh2[s6 * 32 + lane]);
        uint2 p7 = __ldg(&xh2[s7 * 32 + lane]);
        acc_h2(a0, p0); acc_h2(a1, p1); acc_h2(a2, p2); acc_h2(a3, p3);
        acc_h2(a0, p4); acc_h2(a1, p5); acc_h2(a2, p6); acc_h2(a3, p7);
    }
    for (; e + 3 < end; e += 4) {
        int s0 = g_srcs[e],     s1 = g_srcs[e + 1];
        int s2 = g_srcs[e + 2], s3 = g_srcs[e + 3];
        uint2 p0 = __ldg(&xh2[s0 * 32 + lane]);
        uint2 p1 = __ldg(&xh2[s1 * 32 + lane]);
        uint2 p2 = __ldg(&xh2[s2 * 32 + lane]);
        uint2 p3 = __ldg(&xh2[s3 * 32 + lane]);
        acc_h2(a0, p0); acc_h2(a1, p1); acc_h2(a2, p2); acc_h2(a3, p3);
    }
    for (; e < end; e++) {
        uint2 p0 = __ldg(&xh2[g_srcs[e] * 32 + lane]);
        acc_h2(a0, p0);
    }

    const float inv = 1.0f / fmaxf((float)cnt, 1.0f);
    float4 r;
    r.x = (a0.x + a1.x + a2.x + a3.x) * inv;
    r.y = (a0.y + a1.y + a2.y + a3.y) * inv;
    r.z = (a0.z + a1.z + a2.z + a3.z) * inv;
    r.w = (a0.w + a1.w + a2.w + a3.w) * inv;
    reinterpret_cast<float4*>(g_agg)[(size_t)node * 32 + lane] = r;
}

// -------------------- 6) persistent double-buffered GEMM -------------------
__device__ __forceinline__ void issue_h_tile(int tile, float* buf, int tid) {
    const int m0 = tile * TILE_M;
    const float4* aggbase = reinterpret_cast<const float4*>(g_agg);
    #pragma unroll
    for (int j = 0; j < 16; j++) {
        const int i = tid + j * 256;
        const int r = i >> 5;
        const int c = i & 31;
        const int m = min(m0 + r, N_NODES - 1);
        const float4* src = aggbase + (size_t)m * 32 + c;
        unsigned saddr = (unsigned)__cvta_generic_to_shared(buf + i * 4);
        asm volatile("cp.async.cg.shared.global [%0], [%1], 16;"
                     :: "r"(saddr), "l"(src));
    }
    asm volatile("cp.async.commit_group;");
}

__global__ void __launch_bounds__(256, 1)
gemm_kernel(float* __restrict__ out, const float* __restrict__ W,
            const float* __restrict__ b) {
    extern __shared__ float sm[];
    float* Wsm   = sm;
    float* Hbuf0 = sm + IN_F * OUT_F;
    float* Hbuf1 = Hbuf0 + TILE_M * IN_F;

    const int tid = threadIdx.x;

    int tile0 = blockIdx.x;
    if (tile0 < N_TILES) issue_h_tile(tile0, Hbuf0, tid);

    #pragma unroll 4
    for (int i = tid; i < OUT_F * IN_F; i += 256) {
        const int n = i >> 7;
        const int k = i & 127;
        Wsm[k * OUT_F + n] = W[i];
    }

    const int rowg = tid >> 4;
    const int colg = tid & 15;
    const int r0   = rowg * 8;
    const int n0   = colg * 8;

    float bb[8];
    #pragma unroll
    for (int j = 0; j < 8; j++) bb[j] = b[n0 + j];

    int it = 0;
    for (int tile = blockIdx.x; tile < N_TILES; tile += NUM_SM, it++) {
        float* cur = (it & 1) ? Hbuf1 : Hbuf0;
        float* nxt = (it & 1) ? Hbuf0 : Hbuf1;
        const int ntile = tile + NUM_SM;
        if (ntile < N_TILES) {
            issue_h_tile(ntile, nxt, tid);
            asm volatile("cp.async.wait_group 1;");
        } else {
            asm volatile("cp.async.wait_group 0;");
        }
        __syncthreads();

        const float4* Hsm4 = reinterpret_cast<const float4*>(cur);

        unsigned long long acc[8][4];
        #pragma unroll
        for (int i = 0; i < 8; i++)
            #pragma unroll
            for (int j = 0; j < 4; j++) acc[i][j] = 0ULL;

        for (int kk = 0; kk < IN_F; kk += 4) {
            float4 h4[8];
            #pragma unroll
            for (int i = 0; i < 8; i++)
                h4[i] = Hsm4[(r0 + i) * 32 + (kk >> 2)];

            #pragma unroll
            for (int j = 0; j < 4; j++) {
                const ulonglong2 wA = *reinterpret_cast<const ulonglong2*>(
                    &Wsm[(kk + j) * OUT_F + n0]);
                const ulonglong2 wB = *reinterpret_cast<const ulonglong2*>(
                    &Wsm[(kk + j) * OUT_F + n0 + 4]);
                #pragma unroll
                for (int i = 0; i < 8; i++) {
                    const float a = (j == 0) ? h4[i].x : (j == 1) ? h4[i].y
                                  : (j == 2) ? h4[i].z : h4[i].w;
                    unsigned long long aa;
                    asm("mov.b64 %0, {%1, %1};" : "=l"(aa) : "f"(a));
                    asm("fma.rn.f32x2 %0, %1, %2, %0;" : "+l"(acc[i][0]) : "l"(aa), "l"(wA.x));
                    asm("fma.rn.f32x2 %0, %1, %2, %0;" : "+l"(acc[i][1]) : "l"(aa), "l"(wA.y));
                    asm("fma.rn.f32x2 %0, %1, %2, %0;" : "+l"(acc[i][2]) : "l"(aa), "l"(wB.x));
                    asm("fma.rn.f32x2 %0, %1, %2, %0;" : "+l"(acc[i][3]) : "l"(aa), "l"(wB.y));
                }
            }
        }

        const int m0 = tile * TILE_M;
        #pragma unroll
        for (int i = 0; i < 8; i++) {
            const int m = m0 + r0 + i;
            if (m < N_NODES) {
                float lo, hi;
                float o[8];
                #pragma unroll
                for (int j = 0; j < 4; j++) {
                    asm("mov.b64 {%0, %1}, %2;" : "=f"(lo), "=f"(hi) : "l"(acc[i][j]));
                    o[2 * j]     = lo + bb[2 * j];
                    o[2 * j + 1] = hi + bb[2 * j + 1];
                }
                float4* orow = reinterpret_cast<float4*>(out + (size_t)m * OUT_F + n0);
                orow[0] = make_float4(o[0], o[1], o[2], o[3]);
                orow[1] = make_float4(o[4], o[5], o[6], o[7]);
            }
        }
        __syncthreads();
    }
}

// ---------------------------------------------------------------------------
extern "C" void kernel_launch(void* const* d_in, const int* in_sizes, int n_in,
                              void* d_out, int out_size) {
    const float* x  = nullptr;
    const int*   ei = nullptr;
    const float* W  = nullptr;
    const float* b  = nullptr;

    for (int i = 0; i < n_in; i++) {
        switch (in_sizes[i]) {
            case N_NODES * IN_F:  x  = (const float*)d_in[i]; break;
            case 2 * N_EDGES:     ei = (const int*)d_in[i];   break;
            case OUT_F * IN_F:    W  = (const float*)d_in[i]; break;
            case OUT_F:           b  = (const float*)d_in[i]; break;
            default: break;
        }
    }

    float* out = (float*)d_out;

    convert_zero_kernel<<<2048, 256>>>(reinterpret_cast<const float4*>(x));
    hist_kernel<<<(N_EDGES / 4 + 255) / 256, 256>>>(ei);
    scanA_kernel<<<SCAN_B, SCAN_T>>>();
    scanB_kernel<<<SCAN_B, SCAN_T>>>();
    fill_kernel<<<(N_EDGES / 4 + 255) / 256, 256>>>(ei);

    const int agg_blocks = (N_NODES * 32 + 255) / 256;   // 6250
    agg_kernel<<<agg_blocks, 256>>>();

    const int smem_bytes = 3 * IN_F * OUT_F * (int)sizeof(float);  // 192KB
    cudaFuncSetAttribute(gemm_kernel, cudaFuncAttributeMaxDynamicSharedMemorySize,
                         smem_bytes);
    gemm_kernel<<<NUM_SM, 256, smem_bytes>>>(out, W, b);
}

// round 7
// speedup vs baseline: 1.0553x; 1.0553x over previous
#include <cuda_runtime.h>
#include <stdint.h>

#define N_NODES  50000
#define N_EDGES  800000
#define IN_F     128
#define OUT_F    128

#define SCAN_T   256
#define SCAN_B   ((N_NODES + SCAN_T - 1) / SCAN_T)   // 196

#define NUM_SM   148
#define TILE_M   128
#define N_TILES  ((N_NODES + TILE_M - 1) / TILE_M)   // 391

// -------------------- device scratch (no allocation allowed) ---------------
__device__ __align__(16) float g_agg[N_NODES * IN_F];  // normalized h rows
__device__ int   g_cnt4[4 * N_NODES];  // replicated histograms (stripe = edge%4)
__device__ int   g_cur4[4 * N_NODES];  // replicated fill cursors
__device__ int   g_cnt[N_NODES];       // per-node totals
__device__ int   g_off[N_NODES];       // CSR row start
__device__ int   g_srcs[N_EDGES];      // edge sources grouped by dst
__device__ int   g_bsums[SCAN_B];

// -------------------- 1) histogram (4 edges/thread, 4-way replicated) ------
__global__ void hist_kernel(const int* __restrict__ ei) {
    const int e4 = blockIdx.x * blockDim.x + threadIdx.x;
    if (e4 >= N_EDGES / 4) return;
    int4 d = reinterpret_cast<const int4*>(ei + N_EDGES)[e4];
    d.x = min(max(d.x, 0), N_NODES - 1);
    d.y = min(max(d.y, 0), N_NODES - 1);
    d.z = min(max(d.z, 0), N_NODES - 1);
    d.w = min(max(d.w, 0), N_NODES - 1);
    // each of the 4 edges goes to a different replica array -> contention/4
    atomicAdd(&g_cnt4[0 * N_NODES + d.x], 1);
    atomicAdd(&g_cnt4[1 * N_NODES + d.y], 1);
    atomicAdd(&g_cnt4[2 * N_NODES + d.z], 1);
    atomicAdd(&g_cnt4[3 * N_NODES + d.w], 1);
}

// -------------------- 2) scanA: totals + per-block sums --------------------
__global__ void scanA_kernel() {
    __shared__ int s[SCAN_T];
    const int gid = blockIdx.x * SCAN_T + threadIdx.x;
    int tot = 0;
    if (gid < N_NODES) {
        tot = g_cnt4[gid] + g_cnt4[N_NODES + gid]
            + g_cnt4[2 * N_NODES + gid] + g_cnt4[3 * N_NODES + gid];
        g_cnt[gid] = tot;
    }
    s[threadIdx.x] = tot;
    __syncthreads();
    #pragma unroll
    for (int o = SCAN_T / 2; o > 0; o >>= 1) {
        if (threadIdx.x < o) s[threadIdx.x] += s[threadIdx.x + o];
        __syncthreads();
    }
    if (threadIdx.x == 0) g_bsums[blockIdx.x] = s[0];
}

// -------------------- 3) scanB: exclusive scan + replica cursor bases ------
__global__ void scanB_kernel() {
    __shared__ int sb[SCAN_T];
    __shared__ int st[SCAN_T];
    const int tid = threadIdx.x;

    int bv = (tid < SCAN_B) ? g_bsums[tid] : 0;
    sb[tid] = bv;
    __syncthreads();
    #pragma unroll
    for (int o = 1; o < SCAN_T; o <<= 1) {
        int t = (tid >= o) ? sb[tid - o] : 0;
        __syncthreads();
        sb[tid] += t;
        __syncthreads();
    }
    const int base = (blockIdx.x > 0) ? sb[blockIdx.x - 1] : 0;

    const int gid = blockIdx.x * SCAN_T + tid;
    int c = (gid < N_NODES) ? g_cnt[gid] : 0;
    st[tid] = c;
    __syncthreads();
    #pragma unroll
    for (int o = 1; o < SCAN_T; o <<= 1) {
        int t = (tid >= o) ? st[tid - o] : 0;
        __syncthreads();
        st[tid] += t;
        __syncthreads();
    }
    if (gid < N_NODES) {
        const int excl = base + st[tid] - c;
        const int c0 = g_cnt4[gid];
        const int c1 = g_cnt4[N_NODES + gid];
        const int c2 = g_cnt4[2 * N_NODES + gid];
        g_off[gid] = excl;
        g_cur4[gid]                 = excl;
        g_cur4[N_NODES + gid]       = excl + c0;
        g_cur4[2 * N_NODES + gid]   = excl + c0 + c1;
        g_cur4[3 * N_NODES + gid]   = excl + c0 + c1 + c2;
    }
}

// -------------------- 4) bucket-fill (4 edges/thread, replicated cursors) --
__global__ void fill_kernel(const int* __restrict__ ei) {
    const int e4 = blockIdx.x * blockDim.x + threadIdx.x;
    if (e4 >= N_EDGES / 4) return;
    int4 s = reinterpret_cast<const int4*>(ei)[e4];
    int4 d = reinterpret_cast<const int4*>(ei + N_EDGES)[e4];
    s.x = min(max(s.x, 0), N_NODES - 1);
    s.y = min(max(s.y, 0), N_NODES - 1);
    s.z = min(max(s.z, 0), N_NODES - 1);
    s.w = min(max(s.w, 0), N_NODES - 1);
    d.x = min(max(d.x, 0), N_NODES - 1);
    d.y = min(max(d.y, 0), N_NODES - 1);
    d.z = min(max(d.z, 0), N_NODES - 1);
    d.w = min(max(d.w, 0), N_NODES - 1);
    int p0 = atomicAdd(&g_cur4[0 * N_NODES + d.x], 1);
    int p1 = atomicAdd(&g_cur4[1 * N_NODES + d.y], 1);
    int p2 = atomicAdd(&g_cur4[2 * N_NODES + d.z], 1);
    int p3 = atomicAdd(&g_cur4[3 * N_NODES + d.w], 1);
    g_srcs[p0] = s.x;
    g_srcs[p1] = s.y;
    g_srcs[p2] = s.z;
    g_srcs[p3] = s.w;
}

// -------------------- 5) gather-aggregate: one warp per node (fp32) --------
__global__ void __launch_bounds__(256)
agg_kernel(const float4* __restrict__ x4) {
    const int node = (blockIdx.x * blockDim.x + threadIdx.x) >> 5;
    if (node >= N_NODES) return;
    const int lane = threadIdx.x & 31;

    const int start = g_off[node];
    const int cnt   = g_cnt[node];
    const int end   = start + cnt;

    float4 a0 = make_float4(0.f, 0.f, 0.f, 0.f);
    float4 a1 = make_float4(0.f, 0.f, 0.f, 0.f);
    float4 a2 = make_float4(0.f, 0.f, 0.f, 0.f);
    float4 a3 = make_float4(0.f, 0.f, 0.f, 0.f);

    int e = start;
    for (; e + 7 < end; e += 8) {
        int s0 = g_srcs[e],     s1 = g_srcs[e + 1];
        int s2 = g_srcs[e + 2], s3 = g_srcs[e + 3];
        int s4 = g_srcs[e + 4], s5 = g_srcs[e + 5];
        int s6 = g_srcs[e + 6], s7 = g_srcs[e + 7];
        float4 v0 = __ldg(&x4[s0 * 32 + lane]);
        float4 v1 = __ldg(&x4[s1 * 32 + lane]);
        float4 v2 = __ldg(&x4[s2 * 32 + lane]);
        float4 v3 = __ldg(&x4[s3 * 32 + lane]);
        float4 v4 = __ldg(&x4[s4 * 32 + lane]);
        float4 v5 = __ldg(&x4[s5 * 32 + lane]);
        float4 v6 = __ldg(&x4[s6 * 32 + lane]);
        float4 v7 = __ldg(&x4[s7 * 32 + lane]);
        a0.x += v0.x; a0.y += v0.y; a0.z += v0.z; a0.w += v0.w;
        a1.x += v1.x; a1.y += v1.y; a1.z += v1.z; a1.w += v1.w;
        a2.x += v2.x; a2.y += v2.y; a2.z += v2.z; a2.w += v2.w;
        a3.x += v3.x; a3.y += v3.y; a3.z += v3.z; a3.w += v3.w;
        a0.x += v4.x; a0.y += v4.y; a0.z += v4.z; a0.w += v4.w;
        a1.x += v5.x; a1.y += v5.y; a1.z += v5.z; a1.w += v5.w;
        a2.x += v6.x; a2.y += v6.y; a2.z += v6.z; a2.w += v6.w;
        a3.x += v7.x; a3.y += v7.y; a3.z += v7.z; a3.w += v7.w;
    }
    // predicated tail: up to 7 edges, all loads issue together (MLP=7)
    const int rem = end - e;
    if (rem > 0) {
        int idx[7];
        #pragma unroll
        for (int i = 0; i < 7; i++)
            idx[i] = (i < rem) ? g_srcs[e + i] : 0;
        float4 v[7];
        #pragma unroll
        for (int i = 0; i < 7; i++)
            if (i < rem) v[i] = __ldg(&x4[idx[i] * 32 + lane]);
        #pragma unroll
        for (int i = 0; i < 7; i++)
            if (i < rem) {
                float4* a = (i & 3) == 0 ? &a0 : (i & 3) == 1 ? &a1
                          : (i & 3) == 2 ? &a2 : &a3;
                a->x += v[i].x; a->y += v[i].y; a->z += v[i].z; a->w += v[i].w;
            }
    }

    const float inv = 1.0f / fmaxf((float)cnt, 1.0f);
    float4 r;
    r.x = (a0.x + a1.x + a2.x + a3.x) * inv;
    r.y = (a0.y + a1.y + a2.y + a3.y) * inv;
    r.z = (a0.z + a1.z + a2.z + a3.z) * inv;
    r.w = (a0.w + a1.w + a2.w + a3.w) * inv;
    reinterpret_cast<float4*>(g_agg)[(size_t)node * 32 + lane] = r;
}

// -------------------- 6) persistent double-buffered GEMM -------------------
__device__ __forceinline__ void issue_h_tile(int tile, float* buf, int tid) {
    const int m0 = tile * TILE_M;
    const float4* aggbase = reinterpret_cast<const float4*>(g_agg);
    #pragma unroll
    for (int j = 0; j < 16; j++) {
        const int i = tid + j * 256;
        const int r = i >> 5;
        const int c = i & 31;
        const int m = min(m0 + r, N_NODES - 1);
        const float4* src = aggbase + (size_t)m * 32 + c;
        unsigned saddr = (unsigned)__cvta_generic_to_shared(buf + i * 4);
        asm volatile("cp.async.cg.shared.global [%0], [%1], 16;"
                     :: "r"(saddr), "l"(src));
    }
    asm volatile("cp.async.commit_group;");
}

__global__ void __launch_bounds__(256, 1)
gemm_kernel(float* __restrict__ out, const float* __restrict__ W,
            const float* __restrict__ b) {
    extern __shared__ float sm[];
    float* Wsm   = sm;
    float* Hbuf0 = sm + IN_F * OUT_F;
    float* Hbuf1 = Hbuf0 + TILE_M * IN_F;

    const int tid = threadIdx.x;

    int tile0 = blockIdx.x;
    if (tile0 < N_TILES) issue_h_tile(tile0, Hbuf0, tid);

    #pragma unroll 4
    for (int i = tid; i < OUT_F * IN_F; i += 256) {
        const int n = i >> 7;
        const int k = i & 127;
        Wsm[k * OUT_F + n] = W[i];
    }

    const int rowg = tid >> 4;
    const int colg = tid & 15;
    const int r0   = rowg * 8;
    const int n0   = colg * 8;

    float bb[8];
    #pragma unroll
    for (int j = 0; j < 8; j++) bb[j] = b[n0 + j];

    int it = 0;
    for (int tile = blockIdx.x; tile < N_TILES; tile += NUM_SM, it++) {
        float* cur = (it & 1) ? Hbuf1 : Hbuf0;
        float* nxt = (it & 1) ? Hbuf0 : Hbuf1;
        const int ntile = tile + NUM_SM;
        if (ntile < N_TILES) {
            issue_h_tile(ntile, nxt, tid);
            asm volatile("cp.async.wait_group 1;");
        } else {
            asm volatile("cp.async.wait_group 0;");
        }
        __syncthreads();

        const float4* Hsm4 = reinterpret_cast<const float4*>(cur);

        unsigned long long acc[8][4];
        #pragma unroll
        for (int i = 0; i < 8; i++)
            #pragma unroll
            for (int j = 0; j < 4; j++) acc[i][j] = 0ULL;

        for (int kk = 0; kk < IN_F; kk += 4) {
            float4 h4[8];
            #pragma unroll
            for (int i = 0; i < 8; i++)
                h4[i] = Hsm4[(r0 + i) * 32 + (kk >> 2)];

            #pragma unroll
            for (int j = 0; j < 4; j++) {
                const ulonglong2 wA = *reinterpret_cast<const ulonglong2*>(
                    &Wsm[(kk + j) * OUT_F + n0]);
                const ulonglong2 wB = *reinterpret_cast<const ulonglong2*>(
                    &Wsm[(kk + j) * OUT_F + n0 + 4]);
                #pragma unroll
                for (int i = 0; i < 8; i++) {
                    const float a = (j == 0) ? h4[i].x : (j == 1) ? h4[i].y
                                  : (j == 2) ? h4[i].z : h4[i].w;
                    unsigned long long aa;
                    asm("mov.b64 %0, {%1, %1};" : "=l"(aa) : "f"(a));
                    asm("fma.rn.f32x2 %0, %1, %2, %0;" : "+l"(acc[i][0]) : "l"(aa), "l"(wA.x));
                    asm("fma.rn.f32x2 %0, %1, %2, %0;" : "+l"(acc[i][1]) : "l"(aa), "l"(wA.y));
                    asm("fma.rn.f32x2 %0, %1, %2, %0;" : "+l"(acc[i][2]) : "l"(aa), "l"(wB.x));
                    asm("fma.rn.f32x2 %0, %1, %2, %0;" : "+l"(acc[i][3]) : "l"(aa), "l"(wB.y));
                }
            }
        }

        const int m0 = tile * TILE_M;
        #pragma unroll
        for (int i = 0; i < 8; i++) {
            const int m = m0 + r0 + i;
            if (m < N_NODES) {
                float lo, hi;
                float o[8];
                #pragma unroll
                for (int j = 0; j < 4; j++) {
                    asm("mov.b64 {%0, %1}, %2;" : "=f"(lo), "=f"(hi) : "l"(acc[i][j]));
                    o[2 * j]     = lo + bb[2 * j];
                    o[2 * j + 1] = hi + bb[2 * j + 1];
                }
                float4* orow = reinterpret_cast<float4*>(out + (size_t)m * OUT_F + n0);
                orow[0] = make_float4(o[0], o[1], o[2], o[3]);
                orow[1] = make_float4(o[4], o[5], o[6], o[7]);
            }
        }
        __syncthreads();
    }
}

// ---------------------------------------------------------------------------
extern "C" void kernel_launch(void* const* d_in, const int* in_sizes, int n_in,
                              void* d_out, int out_size) {
    const float* x  = nullptr;
    const int*   ei = nullptr;
    const float* W  = nullptr;
    const float* b  = nullptr;

    for (int i = 0; i < n_in; i++) {
        switch (in_sizes[i]) {
            case N_NODES * IN_F:  x  = (const float*)d_in[i]; break;
            case 2 * N_EDGES:     ei = (const int*)d_in[i];   break;
            case OUT_F * IN_F:    W  = (const float*)d_in[i]; break;
            case OUT_F:           b  = (const float*)d_in[i]; break;
            default: break;
        }
    }

    float* out = (float*)d_out;

    void* cnt4_ptr = nullptr;
    cudaGetSymbolAddress(&cnt4_ptr, g_cnt4);
    cudaMemsetAsync(cnt4_ptr, 0, 4 * N_NODES * sizeof(int));

    hist_kernel<<<(N_EDGES / 4 + 255) / 256, 256>>>(ei);
    scanA_kernel<<<SCAN_B, SCAN_T>>>();
    scanB_kernel<<<SCAN_B, SCAN_T>>>();
    fill_kernel<<<(N_EDGES / 4 + 255) / 256, 256>>>(ei);

    const int agg_blocks = (N_NODES * 32 + 255) / 256;   // 6250
    agg_kernel<<<agg_blocks, 256>>>(reinterpret_cast<const float4*>(x));

    const int smem_bytes = 3 * IN_F * OUT_F * (int)sizeof(float);  // 192KB
    cudaFuncSetAttribute(gemm_kernel, cudaFuncAttributeMaxDynamicSharedMemorySize,
                         smem_bytes);
    gemm_kernel<<<NUM_SM, 256, smem_bytes>>>(out, W, b);
}